// round 12
// baseline (speedup 1.0000x reference)
#include <cuda_runtime.h>
#include <cstdint>

// g_tree: heap-indexed subtree sums, levels 0..16 only (indices [0, 2^17)).
// g_rec: 4-level descent records. For node i at levels {0,4,8,12,16},
//   g_rec[4i..4i+3] packs {t[2i]; t[4i],t[4i+2]; t[8i+evens]; t[16i+evens]}
//   (15 floats + pad = 64B): one 64B load decides 4 levels.
//   Level-16 records are emitted by build_lower from block-local smem (so
//   tree levels 17..20 are never materialized); the 4369 records at levels
//   0/4/8/12 are emitted by build_top. Levels 21..24 + the priority come
//   from a 64B burst of the 16 leaves under the level-20 node. All sums use
//   the identical left+right pairing as reshape(-1,2).sum(axis=1) =>
//   bitwise-exact descent.
#define BOUND (1 << 24)
__device__ float  g_tree[1 << 17];   // 512 KB (levels 0..16)
__device__ float4 g_rec[1 << 19];    // 8 MB   (entries 4*i, i < 2^17)

// ---------------------------------------------------------------------------
// build_lower: each block reduces 4096 contiguous leaves. Stores levels
// 16..12 to g_tree and emits the block's 16 level-16 records from smem.
// ---------------------------------------------------------------------------
__global__ __launch_bounds__(256) void build_lower(const float* __restrict__ leaf) {
    const int b = blockIdx.x;           // 4096 blocks
    const int t = threadIdx.x;
    const int lane = t & 31;
    const int w = t >> 5;               // 8 warps
    __shared__ float s20[256], s19[128], s18[64], s17[32];

    const float4* __restrict__ in = reinterpret_cast<const float4*>(leaf) + (size_t)b * 1024;

#pragma unroll
    for (int r = 0; r < 4; ++r) {
        const int q = r * 256 + t;                    // level-22 node id in block
        float4 a = in[q];                             // coalesced LDG.128
        float v = (a.x + a.y) + (a.z + a.w);          // level-22 value (exact pairing)
        float u;
        u = __shfl_down_sync(0xffffffffu, v, 1);  v += u;   // level 21
        u = __shfl_down_sync(0xffffffffu, v, 2);  v += u;   // level 20
        if (!(lane & 3))  s20[r * 64 + w * 8 + (lane >> 2)] = v;
        u = __shfl_down_sync(0xffffffffu, v, 4);  v += u;   // level 19
        if (!(lane & 7))  s19[r * 32 + w * 4 + (lane >> 3)] = v;
        u = __shfl_down_sync(0xffffffffu, v, 8);  v += u;   // level 18
        if (!(lane & 15)) s18[r * 16 + w * 2 + (lane >> 4)] = v;
        u = __shfl_down_sync(0xffffffffu, v, 16); v += u;   // level 17
        if (lane == 0) s17[r * 8 + w] = v;
    }
    __syncthreads();

    // Warp 0 finishes levels 16..12 from the 32 level-17 values.
    if (w == 0) {
        float v = s17[lane];
        float u;
        float* g16 = g_tree + (1u << 16) + (size_t)b * 16;
        float* g15 = g_tree + (1u << 15) + (size_t)b * 8;
        float* g14 = g_tree + (1u << 14) + (size_t)b * 4;
        float* g13 = g_tree + (1u << 13) + (size_t)b * 2;
        float* g12 = g_tree + (1u << 12) + (size_t)b;
        u = __shfl_down_sync(0xffffffffu, v, 1);  v += u;
        if (!(lane & 1))  g16[lane >> 1] = v;
        u = __shfl_down_sync(0xffffffffu, v, 2);  v += u;
        if (!(lane & 3))  g15[lane >> 2] = v;
        u = __shfl_down_sync(0xffffffffu, v, 4);  v += u;
        if (!(lane & 7))  g14[lane >> 3] = v;
        u = __shfl_down_sync(0xffffffffu, v, 8);  v += u;
        if (!(lane & 15)) g13[lane >> 4] = v;
        u = __shfl_down_sync(0xffffffffu, v, 16); v += u;
        if (lane == 0)    g12[0] = v;
    }
    __syncthreads();

    // Emit the 16 level-16 records of this block straight from smem.
    if (t < 16) {
        const int j = t;
        const size_t i = (size_t)(1u << 16) + (size_t)b * 16 + j;
        float4* r = &g_rec[4 * i];
        r[0] = make_float4(s17[2 * j], s18[4 * j], s18[4 * j + 2], s19[8 * j]);
        r[1] = make_float4(s19[8 * j + 2], s19[8 * j + 4], s19[8 * j + 6], s20[16 * j]);
        r[2] = make_float4(s20[16 * j + 2], s20[16 * j + 4], s20[16 * j + 6], s20[16 * j + 8]);
        r[3] = make_float4(s20[16 * j + 10], s20[16 * j + 12], s20[16 * j + 14], 0.0f);
    }
}

// ---------------------------------------------------------------------------
// build_top: 1 block, 1024 threads. Builds levels 11..0 from level 12, stores
// heap [0, 4096), then emits the 4369 records at levels 0/4/8/12 (small ones
// from the smem heap, level-12 ones from the L2-hot g_tree levels 13..16).
// ---------------------------------------------------------------------------
__device__ __forceinline__ void emit_rec(const float* __restrict__ src, size_t i) {
    float4* r = &g_rec[4 * i];
    r[0] = make_float4(src[2 * i], src[4 * i], src[4 * i + 2], src[8 * i]);
    r[1] = make_float4(src[8 * i + 2], src[8 * i + 4], src[8 * i + 6], src[16 * i]);
    r[2] = make_float4(src[16 * i + 2], src[16 * i + 4], src[16 * i + 6], src[16 * i + 8]);
    r[3] = make_float4(src[16 * i + 10], src[16 * i + 12], src[16 * i + 14], 0.0f);
}

__global__ __launch_bounds__(1024) void build_top() {
    __shared__ float s[8192];
    const int t = threadIdx.x;
    float4* s4p = reinterpret_cast<float4*>(s);
    const float4* g4 = reinterpret_cast<const float4*>(g_tree);
    for (int i = t; i < 1024; i += 1024) s4p[1024 + i] = g4[1024 + i];  // level 12
    if (t == 0) s[0] = 0.0f;
    __syncthreads();
#pragma unroll
    for (int n = 2048; n >= 1; n >>= 1) {
        for (int i = t; i < n; i += 1024)
            s[n + i] = s[2 * (n + i)] + s[2 * (n + i) + 1];
        __syncthreads();
    }
    // Store heap [0, 4096) via float4.
    float4* g4w = reinterpret_cast<float4*>(g_tree);
    for (int i = t; i < 1024; i += 1024) g4w[i] = s4p[i];

    // Records at level 12 (need tree levels 13..16 => g_tree).
    for (int i = 4096 + t; i < 8192; i += 1024) emit_rec(g_tree, (size_t)i);
    // Records at levels 8, 4, 0 (need tree levels <= 12 => smem heap).
    if (t < 256) emit_rec(s, (size_t)(256 + t));
    if (t < 16)  emit_rec(s, (size_t)(16 + t));
    if (t == 0)  emit_rec(s, (size_t)1);
}

// ---------------------------------------------------------------------------
// Descend: pure-global (no smem/barriers), 512 blocks x 128 threads.
// 5 dependent 64B record loads resolve levels 1..20, then one 64B leaf burst
// resolves levels 21..24 + the priority. 6 dependent memory rounds.
// ---------------------------------------------------------------------------
__global__ __launch_bounds__(128) void descend(const float* __restrict__ leaf,
                                               const float* __restrict__ frac,
                                               float* __restrict__ out,
                                               int batch) {
    const int q = blockIdx.x * 128 + threadIdx.x;
    if (q >= batch) return;

    float v = frac[q] * __ldg(&g_tree[1]);
    int idx = 1;

#pragma unroll
    for (int r5 = 0; r5 < 5; ++r5) {
        const float4* rp = g_rec + 4 * (size_t)idx;
        float4 r0 = __ldg(rp);
        float4 r1 = __ldg(rp + 1);
        float4 r2 = __ldg(rp + 2);
        float4 r3 = __ldg(rp + 3);

        bool x1 = (r0.x < v);                 v = x1 ? (v - r0.x) : v;   // level +1
        float lb = x1 ? r0.z : r0.y;
        bool x2 = (lb < v);                   v = x2 ? (v - lb) : v;     // level +2
        float lc = x1 ? (x2 ? r1.z : r1.y) : (x2 ? r1.x : r0.w);
        bool x3 = (lc < v);                   v = x3 ? (v - lc) : v;     // level +3
        float e0 = x3 ? r2.x : r1.w;
        float e1 = x3 ? r2.z : r2.y;
        float e2 = x3 ? r3.x : r2.w;
        float e3 = x3 ? r3.z : r3.y;
        float ld = x1 ? (x2 ? e3 : e2) : (x2 ? e1 : e0);
        bool x4 = (ld < v);                   v = x4 ? (v - ld) : v;     // level +4

        idx = 16 * idx + 8 * (int)x1 + 4 * (int)x2 + 2 * (int)x3 + (int)x4;
    }

    // idx at level 20. Burst the 16 leaves under it (64B aligned, 1 line).
    const int base = (idx << 4) - BOUND;
    const float4* lp = reinterpret_cast<const float4*>(leaf + base);
    float4 A = __ldg(lp);
    float4 B = __ldg(lp + 1);
    float4 C = __ldg(lp + 2);
    float4 D = __ldg(lp + 3);

    float s8_0 = A.x + A.y, s8_2 = B.x + B.y;
    float s8_4 = C.x + C.y, s8_6 = D.x + D.y;
    float s4_0 = s8_0 + (A.z + A.w), s4_1 = s8_2 + (B.z + B.w);
    float s4_2 = s8_4 + (C.z + C.w);
    float s2_0 = s4_0 + s4_1;

    bool r1 = (s2_0 < v); v = r1 ? (v - s2_0) : v;          // level 21
    float l22 = r1 ? s4_2 : s4_0;
    bool r2 = (l22 < v);  v = r2 ? (v - l22) : v;           // level 22
    float l23 = r1 ? (r2 ? s8_6 : s8_4) : (r2 ? s8_2 : s8_0);
    bool r3 = (l23 < v);  v = r3 ? (v - l23) : v;           // level 23
    float4 P = r1 ? C : A;
    float4 Q = r1 ? D : B;
    float4 R = r2 ? Q : P;
    float e0 = r3 ? R.z : R.x;
    float e1 = r3 ? R.w : R.y;
    bool r4 = (e0 < v);                                     // level 24
    float prio = r4 ? e1 : e0;

    const int leafIdx = base + 8 * (int)r1 + 4 * (int)r2 + 2 * (int)r3 + (int)r4;
    out[q] = (float)leafIdx;      // exact in f32 (< 2^24)
    out[batch + q] = prio;
}

extern "C" void kernel_launch(void* const* d_in, const int* in_sizes, int n_in,
                              void* d_out, int out_size) {
    const float* leaf = (const float*)d_in[0];
    const float* frac = (const float*)d_in[1];
    float* out = (float*)d_out;
    const int batch = in_sizes[1];

    build_lower<<<BOUND / 4096, 256>>>(leaf);
    build_top<<<1, 1024>>>();
    descend<<<(batch + 127) / 128, 128>>>(leaf, frac, out, batch);
}

// round 13
// speedup vs baseline: 1.0564x; 1.0564x over previous
#include <cuda_runtime.h>
#include <cstdint>

// g_tree: heap-indexed subtree sums, levels 0..16 only (indices [0, 2^17)).
// g_rec: 4-level descent records. For node i at levels {0,4,8,12,16},
//   g_rec[4i..4i+3] packs {t[2i]; t[4i],t[4i+2]; t[8i+evens]; t[16i+evens]}
//   (15 floats + pad = 64B): one 64B load decides 4 levels.
//   Level-16 records are emitted by build_lower from block-local smem (tree
//   levels 17..20 are never materialized); the 4369 records at levels
//   0/4/8/12 are emitted by build_top with vectorized gathers. Levels 21..24
//   + the priority come from a 64B burst of the 16 leaves under the level-20
//   node. All sums use the identical left+right pairing as
//   reshape(-1,2).sum(axis=1) => bitwise-exact descent.
#define BOUND (1 << 24)
__device__ float  g_tree[1 << 17];   // 512 KB (levels 0..16)
__device__ float4 g_rec[1 << 19];    // 8 MB   (entries 4*i, i < 2^17)

// ---------------------------------------------------------------------------
// build_lower: each block reduces 4096 contiguous leaves. Stores levels
// 16..12 to g_tree and emits the block's 16 level-16 records from smem.
// ---------------------------------------------------------------------------
__global__ __launch_bounds__(256) void build_lower(const float* __restrict__ leaf) {
    const int b = blockIdx.x;           // 4096 blocks
    const int t = threadIdx.x;
    const int lane = t & 31;
    const int w = t >> 5;               // 8 warps
    __shared__ float s20[256], s19[128], s18[64], s17[32];

    const float4* __restrict__ in = reinterpret_cast<const float4*>(leaf) + (size_t)b * 1024;

#pragma unroll
    for (int r = 0; r < 4; ++r) {
        const int q = r * 256 + t;                    // level-22 node id in block
        float4 a = in[q];                             // coalesced LDG.128
        float v = (a.x + a.y) + (a.z + a.w);          // level-22 value (exact pairing)
        float u;
        u = __shfl_down_sync(0xffffffffu, v, 1);  v += u;   // level 21
        u = __shfl_down_sync(0xffffffffu, v, 2);  v += u;   // level 20
        if (!(lane & 3))  s20[r * 64 + w * 8 + (lane >> 2)] = v;
        u = __shfl_down_sync(0xffffffffu, v, 4);  v += u;   // level 19
        if (!(lane & 7))  s19[r * 32 + w * 4 + (lane >> 3)] = v;
        u = __shfl_down_sync(0xffffffffu, v, 8);  v += u;   // level 18
        if (!(lane & 15)) s18[r * 16 + w * 2 + (lane >> 4)] = v;
        u = __shfl_down_sync(0xffffffffu, v, 16); v += u;   // level 17
        if (lane == 0) s17[r * 8 + w] = v;
    }
    __syncthreads();

    // Warp 0 finishes levels 16..12 from the 32 level-17 values.
    if (w == 0) {
        float v = s17[lane];
        float u;
        float* g16 = g_tree + (1u << 16) + (size_t)b * 16;
        float* g15 = g_tree + (1u << 15) + (size_t)b * 8;
        float* g14 = g_tree + (1u << 14) + (size_t)b * 4;
        float* g13 = g_tree + (1u << 13) + (size_t)b * 2;
        float* g12 = g_tree + (1u << 12) + (size_t)b;
        u = __shfl_down_sync(0xffffffffu, v, 1);  v += u;
        if (!(lane & 1))  g16[lane >> 1] = v;
        u = __shfl_down_sync(0xffffffffu, v, 2);  v += u;
        if (!(lane & 3))  g15[lane >> 2] = v;
        u = __shfl_down_sync(0xffffffffu, v, 4);  v += u;
        if (!(lane & 7))  g14[lane >> 3] = v;
        u = __shfl_down_sync(0xffffffffu, v, 8);  v += u;
        if (!(lane & 15)) g13[lane >> 4] = v;
        u = __shfl_down_sync(0xffffffffu, v, 16); v += u;
        if (lane == 0)    g12[0] = v;
    }
    __syncthreads();

    // Emit the 16 level-16 records of this block straight from smem.
    if (t < 16) {
        const int j = t;
        const size_t i = (size_t)(1u << 16) + (size_t)b * 16 + j;
        float4* r = &g_rec[4 * i];
        r[0] = make_float4(s17[2 * j], s18[4 * j], s18[4 * j + 2], s19[8 * j]);
        r[1] = make_float4(s19[8 * j + 2], s19[8 * j + 4], s19[8 * j + 6], s20[16 * j]);
        r[2] = make_float4(s20[16 * j + 2], s20[16 * j + 4], s20[16 * j + 6], s20[16 * j + 8]);
        r[3] = make_float4(s20[16 * j + 10], s20[16 * j + 12], s20[16 * j + 14], 0.0f);
    }
}

// ---------------------------------------------------------------------------
// build_top: 1 block, 1024 threads. Builds levels 11..0 from level 12, stores
// heap [0, 4096), then emits the 4369 records at levels 0/4/8/12 with
// vectorized gathers (float4 loads; 8 loads/record instead of 15).
// ---------------------------------------------------------------------------
__device__ __forceinline__ void emit_rec_v(const float* __restrict__ src, size_t i) {
    const float  a  = src[2 * i];
    const float4 B  = *reinterpret_cast<const float4*>(&src[4 * i]);
    const float4 C0 = *reinterpret_cast<const float4*>(&src[8 * i]);
    const float4 C1 = *reinterpret_cast<const float4*>(&src[8 * i + 4]);
    const float4 D0 = *reinterpret_cast<const float4*>(&src[16 * i]);
    const float4 D1 = *reinterpret_cast<const float4*>(&src[16 * i + 4]);
    const float4 D2 = *reinterpret_cast<const float4*>(&src[16 * i + 8]);
    const float4 D3 = *reinterpret_cast<const float4*>(&src[16 * i + 12]);
    float4* r = &g_rec[4 * i];
    r[0] = make_float4(a,    B.x,  B.z,  C0.x);
    r[1] = make_float4(C0.z, C1.x, C1.z, D0.x);
    r[2] = make_float4(D0.z, D1.x, D1.z, D2.x);
    r[3] = make_float4(D2.z, D3.x, D3.z, 0.0f);
}

__global__ __launch_bounds__(1024) void build_top() {
    __shared__ float s[8192];
    const int t = threadIdx.x;
    float4* s4p = reinterpret_cast<float4*>(s);
    const float4* g4 = reinterpret_cast<const float4*>(g_tree);
    for (int i = t; i < 1024; i += 1024) s4p[1024 + i] = g4[1024 + i];  // level 12
    if (t == 0) s[0] = 0.0f;
    __syncthreads();
#pragma unroll
    for (int n = 2048; n >= 1; n >>= 1) {
        for (int i = t; i < n; i += 1024)
            s[n + i] = s[2 * (n + i)] + s[2 * (n + i) + 1];
        __syncthreads();
    }
    // Store heap [0, 4096) via float4.
    float4* g4w = reinterpret_cast<float4*>(g_tree);
    for (int i = t; i < 1024; i += 1024) g4w[i] = s4p[i];

    // Records at level 12 (need tree levels 13..16 => g_tree, L2-hot).
    for (int i = 4096 + t; i < 8192; i += 1024) emit_rec_v(g_tree, (size_t)i);
    // Records at levels 8, 4, 0 (need tree levels <= 12 => smem heap).
    if (t < 256) emit_rec_v(s, (size_t)(256 + t));
    if (t < 16)  emit_rec_v(s, (size_t)(16 + t));
    if (t == 0)  emit_rec_v(s, (size_t)1);
}

// ---------------------------------------------------------------------------
// Descend: pure-global (no smem/barriers), 512 blocks x 128 threads.
// 5 dependent 64B record loads resolve levels 1..20, then one 64B leaf burst
// resolves levels 21..24 + the priority. 6 dependent memory rounds.
// ---------------------------------------------------------------------------
__global__ __launch_bounds__(128) void descend(const float* __restrict__ leaf,
                                               const float* __restrict__ frac,
                                               float* __restrict__ out,
                                               int batch) {
    const int q = blockIdx.x * 128 + threadIdx.x;
    if (q >= batch) return;

    float v = frac[q] * __ldg(&g_tree[1]);
    int idx = 1;

#pragma unroll
    for (int r5 = 0; r5 < 5; ++r5) {
        const float4* rp = g_rec + 4 * (size_t)idx;
        float4 r0 = __ldg(rp);
        float4 r1 = __ldg(rp + 1);
        float4 r2 = __ldg(rp + 2);
        float4 r3 = __ldg(rp + 3);

        bool x1 = (r0.x < v);                 v = x1 ? (v - r0.x) : v;   // level +1
        float lb = x1 ? r0.z : r0.y;
        bool x2 = (lb < v);                   v = x2 ? (v - lb) : v;     // level +2
        float lc = x1 ? (x2 ? r1.z : r1.y) : (x2 ? r1.x : r0.w);
        bool x3 = (lc < v);                   v = x3 ? (v - lc) : v;     // level +3
        float e0 = x3 ? r2.x : r1.w;
        float e1 = x3 ? r2.z : r2.y;
        float e2 = x3 ? r3.x : r2.w;
        float e3 = x3 ? r3.z : r3.y;
        float ld = x1 ? (x2 ? e3 : e2) : (x2 ? e1 : e0);
        bool x4 = (ld < v);                   v = x4 ? (v - ld) : v;     // level +4

        idx = 16 * idx + 8 * (int)x1 + 4 * (int)x2 + 2 * (int)x3 + (int)x4;
    }

    // idx at level 20. Burst the 16 leaves under it (64B aligned, 1 line).
    const int base = (idx << 4) - BOUND;
    const float4* lp = reinterpret_cast<const float4*>(leaf + base);
    float4 A = __ldg(lp);
    float4 B = __ldg(lp + 1);
    float4 C = __ldg(lp + 2);
    float4 D = __ldg(lp + 3);

    float s8_0 = A.x + A.y, s8_2 = B.x + B.y;
    float s8_4 = C.x + C.y, s8_6 = D.x + D.y;
    float s4_0 = s8_0 + (A.z + A.w), s4_1 = s8_2 + (B.z + B.w);
    float s4_2 = s8_4 + (C.z + C.w);
    float s2_0 = s4_0 + s4_1;

    bool r1 = (s2_0 < v); v = r1 ? (v - s2_0) : v;          // level 21
    float l22 = r1 ? s4_2 : s4_0;
    bool r2 = (l22 < v);  v = r2 ? (v - l22) : v;           // level 22
    float l23 = r1 ? (r2 ? s8_6 : s8_4) : (r2 ? s8_2 : s8_0);
    bool r3 = (l23 < v);  v = r3 ? (v - l23) : v;           // level 23
    float4 P = r1 ? C : A;
    float4 Q = r1 ? D : B;
    float4 R = r2 ? Q : P;
    float e0 = r3 ? R.z : R.x;
    float e1 = r3 ? R.w : R.y;
    bool r4 = (e0 < v);                                     // level 24
    float prio = r4 ? e1 : e0;

    const int leafIdx = base + 8 * (int)r1 + 4 * (int)r2 + 2 * (int)r3 + (int)r4;
    out[q] = (float)leafIdx;      // exact in f32 (< 2^24)
    out[batch + q] = prio;
}

extern "C" void kernel_launch(void* const* d_in, const int* in_sizes, int n_in,
                              void* d_out, int out_size) {
    const float* leaf = (const float*)d_in[0];
    const float* frac = (const float*)d_in[1];
    float* out = (float*)d_out;
    const int batch = in_sizes[1];

    build_lower<<<BOUND / 4096, 256>>>(leaf);
    build_top<<<1, 1024>>>();
    descend<<<(batch + 127) / 128, 128>>>(leaf, frac, out, batch);
}

// round 15
// speedup vs baseline: 1.7766x; 1.6818x over previous
#include <cuda_runtime.h>
#include <cstdint>

// g_tree: heap-indexed subtree sums, levels 0..12 only (indices [0, 8192)).
// g_rec: 4-level descent records. For node i at levels {0,4,8,12,16},
//   g_rec[4i..4i+3] packs {t[2i]; t[4i],t[4i+2]; t[8i+evens]; t[16i+evens]}
//   (15 floats + pad = 64B): one 64B load decides 4 levels.
//   build_lower emits each block's 16 level-16 records AND its 1 level-12
//   record from block-local smem (tree levels 13..20 never touch global
//   memory); build_top emits the 273 records at levels 0/4/8 from its smem
//   heap. Levels 21..24 + the priority come from a 64B burst of the 16
//   leaves under the level-20 node. All sums use the identical left+right
//   pairing as reshape(-1,2).sum(axis=1) => bitwise-exact descent.
#define BOUND (1 << 24)
__device__ float  g_tree[1 << 13];   // 32 KB (levels 0..12)
__device__ float4 g_rec[1 << 19];    // 8 MB  (entries 4*i, i < 2^17)

// ---------------------------------------------------------------------------
// build_lower: each block reduces 4096 contiguous leaves; emits 17 records
// (16 level-16 + 1 level-12) and stores its level-12 sum to g_tree.
// ---------------------------------------------------------------------------
__global__ __launch_bounds__(256) void build_lower(const float* __restrict__ leaf) {
    const int b = blockIdx.x;           // 4096 blocks
    const int t = threadIdx.x;
    const int lane = t & 31;
    const int w = t >> 5;               // 8 warps
    __shared__ float s20[256], s19[128], s18[64], s17[32];
    __shared__ float s16[16], s15[8], s14[4], s13[2];

    const float4* __restrict__ in = reinterpret_cast<const float4*>(leaf) + (size_t)b * 1024;

#pragma unroll
    for (int r = 0; r < 4; ++r) {
        const int q = r * 256 + t;                    // level-22 node id in block
        float4 a = in[q];                             // coalesced LDG.128
        float v = (a.x + a.y) + (a.z + a.w);          // level-22 value (exact pairing)
        float u;
        u = __shfl_down_sync(0xffffffffu, v, 1);  v += u;   // level 21
        u = __shfl_down_sync(0xffffffffu, v, 2);  v += u;   // level 20
        if (!(lane & 3))  s20[r * 64 + w * 8 + (lane >> 2)] = v;
        u = __shfl_down_sync(0xffffffffu, v, 4);  v += u;   // level 19
        if (!(lane & 7))  s19[r * 32 + w * 4 + (lane >> 3)] = v;
        u = __shfl_down_sync(0xffffffffu, v, 8);  v += u;   // level 18
        if (!(lane & 15)) s18[r * 16 + w * 2 + (lane >> 4)] = v;
        u = __shfl_down_sync(0xffffffffu, v, 16); v += u;   // level 17
        if (lane == 0) s17[r * 8 + w] = v;
    }
    __syncthreads();

    // Warp 0 finishes levels 16..12 from the 32 level-17 values (into smem).
    if (w == 0) {
        float v = s17[lane];
        float u;
        u = __shfl_down_sync(0xffffffffu, v, 1);  v += u;
        if (!(lane & 1))  s16[lane >> 1] = v;
        u = __shfl_down_sync(0xffffffffu, v, 2);  v += u;
        if (!(lane & 3))  s15[lane >> 2] = v;
        u = __shfl_down_sync(0xffffffffu, v, 4);  v += u;
        if (!(lane & 7))  s14[lane >> 3] = v;
        u = __shfl_down_sync(0xffffffffu, v, 8);  v += u;
        if (!(lane & 15)) s13[lane >> 4] = v;
        u = __shfl_down_sync(0xffffffffu, v, 16); v += u;
        if (lane == 0)    g_tree[4096 + b] = v;   // level-12 sum
    }
    __syncthreads();

    // Emit the block's records straight from smem.
    if (t < 16) {
        // 16 level-16 records: node i = 2^16 + b*16 + j.
        const int j = t;
        const size_t i = (size_t)(1u << 16) + (size_t)b * 16 + j;
        float4* r = &g_rec[4 * i];
        r[0] = make_float4(s17[2 * j], s18[4 * j], s18[4 * j + 2], s19[8 * j]);
        r[1] = make_float4(s19[8 * j + 2], s19[8 * j + 4], s19[8 * j + 6], s20[16 * j]);
        r[2] = make_float4(s20[16 * j + 2], s20[16 * j + 4], s20[16 * j + 6], s20[16 * j + 8]);
        r[3] = make_float4(s20[16 * j + 10], s20[16 * j + 12], s20[16 * j + 14], 0.0f);
    } else if (t == 16) {
        // 1 level-12 record: node i = 4096 + b (its levels 13..16 are s13..s16).
        const size_t i = (size_t)4096 + (size_t)b;
        float4* r = &g_rec[4 * i];
        r[0] = make_float4(s13[0],  s14[0],  s14[2],  s15[0]);
        r[1] = make_float4(s15[2],  s15[4],  s15[6],  s16[0]);
        r[2] = make_float4(s16[2],  s16[4],  s16[6],  s16[8]);
        r[3] = make_float4(s16[10], s16[12], s16[14], 0.0f);
    }
}

// ---------------------------------------------------------------------------
// build_top: 1 block, 1024 threads. Builds levels 11..0 from level 12 in
// smem, stores heap [0, 4096), then emits the 273 records at levels 0/4/8
// from the smem heap (no global gathers => no single-SM LSU bottleneck).
// ---------------------------------------------------------------------------
__device__ __forceinline__ void emit_rec_smem(const float* __restrict__ src, size_t i) {
    const float  a  = src[2 * i];
    const float4 B  = *reinterpret_cast<const float4*>(&src[4 * i]);
    const float4 C0 = *reinterpret_cast<const float4*>(&src[8 * i]);
    const float4 C1 = *reinterpret_cast<const float4*>(&src[8 * i + 4]);
    const float4 D0 = *reinterpret_cast<const float4*>(&src[16 * i]);
    const float4 D1 = *reinterpret_cast<const float4*>(&src[16 * i + 4]);
    const float4 D2 = *reinterpret_cast<const float4*>(&src[16 * i + 8]);
    const float4 D3 = *reinterpret_cast<const float4*>(&src[16 * i + 12]);
    float4* r = &g_rec[4 * i];
    r[0] = make_float4(a,    B.x,  B.z,  C0.x);
    r[1] = make_float4(C0.z, C1.x, C1.z, D0.x);
    r[2] = make_float4(D0.z, D1.x, D1.z, D2.x);
    r[3] = make_float4(D2.z, D3.x, D3.z, 0.0f);
}

__global__ __launch_bounds__(1024) void build_top() {
    __shared__ float s[8192];
    const int t = threadIdx.x;
    float4* s4p = reinterpret_cast<float4*>(s);
    const float4* g4 = reinterpret_cast<const float4*>(g_tree);
    for (int i = t; i < 1024; i += 1024) s4p[1024 + i] = g4[1024 + i];  // level 12
    if (t == 0) s[0] = 0.0f;
    __syncthreads();
#pragma unroll
    for (int n = 2048; n >= 1; n >>= 1) {
        for (int i = t; i < n; i += 1024)
            s[n + i] = s[2 * (n + i)] + s[2 * (n + i) + 1];
        __syncthreads();
    }
    // Store heap [0, 4096) via float4 (descend reads g_tree[1] = root).
    float4* g4w = reinterpret_cast<float4*>(g_tree);
    for (int i = t; i < 1024; i += 1024) g4w[i] = s4p[i];

    // Records at levels 8 (256), 4 (16), 0 (1) — all from the smem heap.
    if (t < 256) emit_rec_smem(s, (size_t)(256 + t));
    if (t < 16)  emit_rec_smem(s, (size_t)(16 + t));
    if (t == 0)  emit_rec_smem(s, (size_t)1);
}

// ---------------------------------------------------------------------------
// Descend: pure-global (no smem/barriers), 512 blocks x 128 threads.
// 5 dependent 64B record loads resolve levels 1..20, then one 64B leaf burst
// resolves levels 21..24 + the priority. 6 dependent memory rounds.
// ---------------------------------------------------------------------------
__global__ __launch_bounds__(128) void descend(const float* __restrict__ leaf,
                                               const float* __restrict__ frac,
                                               float* __restrict__ out,
                                               int batch) {
    const int q = blockIdx.x * 128 + threadIdx.x;
    if (q >= batch) return;

    float v = frac[q] * __ldg(&g_tree[1]);
    int idx = 1;

#pragma unroll
    for (int r5 = 0; r5 < 5; ++r5) {
        const float4* rp = g_rec + 4 * (size_t)idx;
        float4 r0 = __ldg(rp);
        float4 r1 = __ldg(rp + 1);
        float4 r2 = __ldg(rp + 2);
        float4 r3 = __ldg(rp + 3);

        bool x1 = (r0.x < v);                 v = x1 ? (v - r0.x) : v;   // level +1
        float lb = x1 ? r0.z : r0.y;
        bool x2 = (lb < v);                   v = x2 ? (v - lb) : v;     // level +2
        float lc = x1 ? (x2 ? r1.z : r1.y) : (x2 ? r1.x : r0.w);
        bool x3 = (lc < v);                   v = x3 ? (v - lc) : v;     // level +3
        float e0 = x3 ? r2.x : r1.w;
        float e1 = x3 ? r2.z : r2.y;
        float e2 = x3 ? r3.x : r2.w;
        float e3 = x3 ? r3.z : r3.y;
        float ld = x1 ? (x2 ? e3 : e2) : (x2 ? e1 : e0);
        bool x4 = (ld < v);                   v = x4 ? (v - ld) : v;     // level +4

        idx = 16 * idx + 8 * (int)x1 + 4 * (int)x2 + 2 * (int)x3 + (int)x4;
    }

    // idx at level 20. Burst the 16 leaves under it (64B aligned, 1 line).
    const int base = (idx << 4) - BOUND;
    const float4* lp = reinterpret_cast<const float4*>(leaf + base);
    float4 A = __ldg(lp);
    float4 B = __ldg(lp + 1);
    float4 C = __ldg(lp + 2);
    float4 D = __ldg(lp + 3);

    float s8_0 = A.x + A.y, s8_2 = B.x + B.y;
    float s8_4 = C.x + C.y, s8_6 = D.x + D.y;
    float s4_0 = s8_0 + (A.z + A.w), s4_1 = s8_2 + (B.z + B.w);
    float s4_2 = s8_4 + (C.z + C.w);
    float s2_0 = s4_0 + s4_1;

    bool r1 = (s2_0 < v); v = r1 ? (v - s2_0) : v;          // level 21
    float l22 = r1 ? s4_2 : s4_0;
    bool r2 = (l22 < v);  v = r2 ? (v - l22) : v;           // level 22
    float l23 = r1 ? (r2 ? s8_6 : s8_4) : (r2 ? s8_2 : s8_0);
    bool r3 = (l23 < v);  v = r3 ? (v - l23) : v;           // level 23
    float4 P = r1 ? C : A;
    float4 Q = r1 ? D : B;
    float4 R = r2 ? Q : P;
    float e0 = r3 ? R.z : R.x;
    float e1 = r3 ? R.w : R.y;
    bool r4 = (e0 < v);                                     // level 24
    float prio = r4 ? e1 : e0;

    const int leafIdx = base + 8 * (int)r1 + 4 * (int)r2 + 2 * (int)r3 + (int)r4;
    out[q] = (float)leafIdx;      // exact in f32 (< 2^24)
    out[batch + q] = prio;
}

extern "C" void kernel_launch(void* const* d_in, const int* in_sizes, int n_in,
                              void* d_out, int out_size) {
    const float* leaf = (const float*)d_in[0];
    const float* frac = (const float*)d_in[1];
    float* out = (float*)d_out;
    const int batch = in_sizes[1];

    build_lower<<<BOUND / 4096, 256>>>(leaf);
    build_top<<<1, 1024>>>();
    descend<<<(batch + 127) / 128, 128>>>(leaf, frac, out, batch);
}